// round 17
// baseline (speedup 1.0000x reference)
#include <cuda_runtime.h>
#include <cuda_bf16.h>
#include <cuda_fp16.h>
#include <cstdint>

#define NN 100000
#define EE 1600000
#define NSEG (NN * 8)
#define AST 72                  // A smem row stride (half): 64 + 8 pad
#define SMEM_BYTES (64*AST*2)   // 9216

__device__ __align__(16) __half   g_y[(size_t)NN * 512];
__device__ __align__(16) float    g_h[(size_t)NN * 64];
__device__ __align__(16) unsigned g_cnt[NSEG];
__device__ __align__(16) unsigned g_off[NSEG + 1];
__device__ __align__(16) unsigned g_woff[NSEG];
__device__ __align__(16) unsigned g_bsum[512];
__device__ __align__(16) int      g_ssrc[EE];
__device__ __align__(16) float    g_acc[128];
__device__ __align__(16) float    g_scale[64];
__device__ __align__(16) float    g_shift[64];
// fragment-packed W (fp16): [nc 9][ns 4][kt 4][lane 32] uint4
__device__ __align__(16) __half g_wp1[9 * 4096];
__device__ __align__(16) __half g_wp2[9 * 4096];

// ---------------- prep ----------------
__global__ void hist_kernel(const int* __restrict__ ei, const int* __restrict__ et,
                            unsigned* __restrict__ cnt) {
    int e = blockIdx.x * 256 + threadIdx.x;
    if (e >= EE) return;
    atomicAdd(cnt + ei[EE + e] * 8 + et[e], 1u);
}

__global__ void scan1(const unsigned* __restrict__ cnt, unsigned* __restrict__ off,
                      unsigned* __restrict__ bsum) {
    __shared__ unsigned sh[256];
    int t = threadIdx.x;
    int base = blockIdx.x * 2048 + t * 8;
    unsigned v[8], s = 0;
#pragma unroll
    for (int j = 0; j < 8; j++) { v[j] = (base + j < NSEG) ? cnt[base + j] : 0u; s += v[j]; }
    sh[t] = s; __syncthreads();
    for (int d = 1; d < 256; d <<= 1) {
        unsigned x = (t >= d) ? sh[t - d] : 0u;
        __syncthreads(); sh[t] += x; __syncthreads();
    }
    if (t == 255) bsum[blockIdx.x] = sh[255];
    unsigned run = sh[t] - s;
#pragma unroll
    for (int j = 0; j < 8; j++)
        if (base + j < NSEG) { off[base + j] = run; run += v[j]; }
}

__global__ void scan2(unsigned* bsum, int nb) {
    __shared__ unsigned sh[512];
    int t = threadIdx.x;
    unsigned v = (t < nb) ? bsum[t] : 0u;
    sh[t] = v; __syncthreads();
    for (int d = 1; d < 512; d <<= 1) {
        unsigned x = (t >= d) ? sh[t - d] : 0u;
        __syncthreads(); sh[t] += x; __syncthreads();
    }
    if (t < nb) bsum[t] = sh[t] - v;
}

__global__ void scan3(unsigned* __restrict__ off, unsigned* __restrict__ woff,
                      const unsigned* __restrict__ bsum) {
    int i = blockIdx.x * 256 + threadIdx.x;
    if (i < NSEG) { unsigned o = off[i] + bsum[i >> 11]; off[i] = o; woff[i] = o; }
    if (i == 0) off[NSEG] = EE;
}

__global__ void sort_kernel(const int* __restrict__ ei, const int* __restrict__ et,
                            unsigned* __restrict__ woff, int* __restrict__ ssrc) {
    int e = blockIdx.x * 256 + threadIdx.x;
    if (e >= EE) return;
    int r = et[e];
    int b = ei[EE + e] * 8 + r;
    unsigned pos = atomicAdd(woff + b, 1u);
    ssrc[pos] = ei[e] * 8 + r;
}

// fragment-pack W (+root as rel 8), fp16.
// elem idx: (((nc*4+ns)*4+kt)*32 + lane)*8 + r*2 + p
__global__ void prep_w(const float* __restrict__ w, const float* __restrict__ root,
                       __half* __restrict__ wp) {
    int i = blockIdx.x * 256 + threadIdx.x;
    if (i >= 9 * 4096) return;
    int nc = i >> 12;
    int rem = i & 4095;
    int ns = rem >> 10;
    int rem2 = rem & 1023;
    int kt = rem2 >> 8;
    int rem3 = rem2 & 255;
    int lane = rem3 >> 3;
    int q = rem3 & 7;
    int r = q >> 1, p = q & 1;
    int n_local = ns * 16 + (r >> 1) * 8 + (lane >> 2);
    int j = nc * 64 + n_local;
    int k = kt * 16 + (lane & 3) * 2 + (r & 1) * 8 + p;
    int rel = j >> 6, o = j & 63;
    float v = (rel < 8) ? w[((size_t)rel * 64 + k) * 64 + o] : root[(size_t)k * 64 + o];
    wp[i] = __float2half(v);
}

// ---------------- GEMM: barrier-free, fp16 1-term, depth-2 B prefetch ----------------
__device__ __forceinline__ uint32_t smem_u32(const void* p) {
    uint32_t a;
    asm("{ .reg .u64 t; cvta.to.shared.u64 t, %1; cvt.u32.u64 %0, t; }" : "=r"(a) : "l"(p));
    return a;
}
__device__ __forceinline__ void ldsm4(unsigned& r0, unsigned& r1, unsigned& r2, unsigned& r3,
                                      uint32_t addr) {
    asm volatile("ldmatrix.sync.aligned.m8n8.x4.shared.b16 {%0,%1,%2,%3}, [%4];"
                 : "=r"(r0), "=r"(r1), "=r"(r2), "=r"(r3) : "r"(addr));
}

#define MMAF16(c0,c1,c2,c3,a0,a1,a2,a3,b0,b1)                                       \
    asm volatile("mma.sync.aligned.m16n8k16.row.col.f32.f16.f16.f32 "               \
                 "{%0,%1,%2,%3},{%4,%5,%6,%7},{%8,%9},{%0,%1,%2,%3};"               \
                 : "+f"(c0), "+f"(c1), "+f"(c2), "+f"(c3)                           \
                 : "r"(a0), "r"(a1), "r"(a2), "r"(a3), "r"(b0), "r"(b1))

template <bool APPLY_BN>
__global__ void __launch_bounds__(256)
gemm_kernel(const float* __restrict__ X, const __half* __restrict__ WP,
            const float* __restrict__ bias,
            const float* __restrict__ bnscale, const float* __restrict__ bnshift,
            __half* __restrict__ Y, float* __restrict__ OUT) {
    extern __shared__ char smem[];
    __half* As = (__half*)smem;          // [64][AST]

    const int tid = threadIdx.x;
    const int wid = tid >> 5, lane = tid & 31;
    const int g = lane >> 2, tig = lane & 3;
    const int warpM = wid & 1, ns = wid >> 1;          // m32 x n16 warp tiles
    const int mbase = blockIdx.x * 64;
    const int mat = lane >> 3, rl = lane & 7;

    // A fill: 64 rows x 32 float2 -> fp16
    for (int it = tid; it < 64 * 32; it += 256) {
        int row = it >> 5, dp = it & 31;
        int grow = mbase + row;
        float2 v = make_float2(0.f, 0.f);
        if (grow < NN) v = *(const float2*)(X + (size_t)grow * 64 + dp * 2);
        if (APPLY_BN) {
            v.x = fmaxf(v.x * bnscale[dp * 2]     + bnshift[dp * 2], 0.f);
            v.y = fmaxf(v.y * bnscale[dp * 2 + 1] + bnshift[dp * 2 + 1], 0.f);
        }
        ((__half2*)(As + row * AST))[dp] = __floats2half2_rn(v.x, v.y);
    }
    __syncthreads();    // the ONLY block barrier

    // A frags -> registers once via ldmatrix
    const uint32_t as_u = smem_u32(As);
    unsigned ah[2][4][4];
#pragma unroll
    for (int mt = 0; mt < 2; mt++) {
#pragma unroll
        for (int kt = 0; kt < 4; kt++) {
            uint32_t row = warpM * 32 + mt * 16 + (mat & 1) * 8 + rl;
            uint32_t kc  = kt * 16 + (mat >> 1) * 8;
            uint32_t ad = as_u + (row * AST + kc) * 2;
            ldsm4(ah[mt][kt][0], ah[mt][kt][1], ah[mt][kt][2], ah[mt][kt][3], ad);
        }
    }

    float c[2][2][4];
#pragma unroll
    for (int mt = 0; mt < 2; mt++)
#pragma unroll
        for (int nt = 0; nt < 2; nt++)
#pragma unroll
            for (int k = 0; k < 4; k++) c[mt][nt][k] = 0.f;

    // B frag base (uint4 units): flat step s = nc*4+kt -> (s>>2)*512 + (s&3)*32
    const uint4* wb = (const uint4*)WP + ns * 128 + lane;
#define BFRAG(s) __ldg(wb + ((s) >> 2) * 512 + ((s) & 3) * 32)

    uint4 b0 = BFRAG(0);
    uint4 b1 = BFRAG(1);

#pragma unroll 1
    for (int nc = 0; nc < 9; nc++) {
#pragma unroll
        for (int kt = 0; kt < 4; kt++) {
            int s = nc * 4 + kt + 2;
            if (s > 35) s = 35;
            uint4 nb = BFRAG(s);

#pragma unroll
            for (int mt = 0; mt < 2; mt++) {
                MMAF16(c[mt][0][0], c[mt][0][1], c[mt][0][2], c[mt][0][3],
                       ah[mt][kt][0], ah[mt][kt][1], ah[mt][kt][2], ah[mt][kt][3],
                       b0.x, b0.y);
                MMAF16(c[mt][1][0], c[mt][1][1], c[mt][1][2], c[mt][1][3],
                       ah[mt][kt][0], ah[mt][kt][1], ah[mt][kt][2], ah[mt][kt][3],
                       b0.z, b0.w);
            }
            b0 = b1; b1 = nb;
        }

        // epilogue for this 64-col chunk
#pragma unroll
        for (int mt = 0; mt < 2; mt++) {
            int row = mbase + warpM * 32 + mt * 16 + g;
#pragma unroll
            for (int nt = 0; nt < 2; nt++) {
                int col = ns * 16 + nt * 8 + 2 * tig;
                float* cc = c[mt][nt];
                if (nc < 8) {
                    size_t base = (size_t)row * 512 + nc * 64 + col;
                    if (row < NN)
                        *(__half2*)(Y + base) = __floats2half2_rn(cc[0], cc[1]);
                    if (row + 8 < NN)
                        *(__half2*)(Y + base + 8 * 512) = __floats2half2_rn(cc[2], cc[3]);
                } else {
                    float2 bb = *(const float2*)(bias + col);
                    if (row < NN)
                        *(float2*)(OUT + (size_t)row * 64 + col) = make_float2(cc[0] + bb.x, cc[1] + bb.y);
                    if (row + 8 < NN)
                        *(float2*)(OUT + (size_t)(row + 8) * 64 + col) = make_float2(cc[2] + bb.x, cc[3] + bb.y);
                }
                cc[0] = cc[1] = cc[2] = cc[3] = 0.f;
            }
        }
    }
#undef BFRAG
}

// ---------------- scatter: warp-per-dst reduce (MLP 8), optional fused BN stats ----------------
template <bool DO_BN>
__global__ void __launch_bounds__(256)
scatter_kernel(const __half* __restrict__ Y, const unsigned* __restrict__ off,
               const int* __restrict__ ssrc, float* __restrict__ OUT,
               float* __restrict__ acc) {
    const int warp = threadIdx.x >> 5, lane = threadIdx.x & 31;
    const int node = blockIdx.x * 8 + warp;   // NN == 8 * gridDim.x exactly

    unsigned ov = (lane < 9) ? __ldg(off + (size_t)node * 8 + lane) : 0u;
    unsigned onext = __shfl_down_sync(0xffffffffu, ov, 1);
    float invv = 1.0f / fmaxf((float)(onext - ov), 1.0f);
    unsigned o0 = __shfl_sync(0xffffffffu, ov, 0);
    unsigned o8 = __shfl_sync(0xffffffffu, ov, 8);

    float accx = 0.f, accy = 0.f;
    for (unsigned e = o0; e < o8; e += 8) {
        int sa[8];
#pragma unroll
        for (int j = 0; j < 8; j++)
            sa[j] = (e + j < o8) ? __ldg(ssrc + e + j) : -1;
        float2 v[8];
#pragma unroll
        for (int j = 0; j < 8; j++) {
            v[j] = make_float2(0.f, 0.f);
            if (sa[j] >= 0) {
                __half2 hv = *(const __half2*)(Y + (size_t)sa[j] * 64 + lane * 2);
                v[j] = __half22float2(hv);
            }
        }
#pragma unroll
        for (int j = 0; j < 8; j++) {
            if (sa[j] >= 0) {
                float iv = __shfl_sync(0xffffffffu, invv, sa[j] & 7);
                accx += v[j].x * iv; accy += v[j].y * iv;
            }
        }
    }
    float2* op = (float2*)(OUT + (size_t)node * 64 + lane * 2);
    float2 cur = *op;
    float ox = cur.x + accx, oy = cur.y + accy;
    *op = make_float2(ox, oy);

    if (DO_BN) {
        __shared__ float sb[8][64], qb[8][64];
        sb[warp][2 * lane] = ox;     sb[warp][2 * lane + 1] = oy;
        qb[warp][2 * lane] = ox * ox; qb[warp][2 * lane + 1] = oy * oy;
        __syncthreads();
        int t = threadIdx.x;
        if (t < 128) {
            int ch = t & 63;
            bool isq = t >= 64;
            float s = 0.f;
#pragma unroll
            for (int w = 0; w < 8; w++) s += isq ? qb[w][ch] : sb[w][ch];
            atomicAdd(acc + (isq ? 64 : 0) + ch, s);
        }
    }
}

__global__ void bn_final(const float* __restrict__ acc, const float* __restrict__ gamma,
                         const float* __restrict__ beta,
                         float* __restrict__ scale, float* __restrict__ shift) {
    int ch = threadIdx.x;
    if (ch >= 64) return;
    const float invN = 1.0f / (float)NN;
    float mu = acc[ch] * invN;
    float var = acc[64 + ch] * invN - mu * mu;
    float sc = gamma[ch] * rsqrtf(var + 1e-5f);
    scale[ch] = sc;
    shift[ch] = beta[ch] - mu * sc;
}

// ---------------- launcher ----------------
extern "C" void kernel_launch(void* const* d_in, const int* in_sizes, int n_in,
                              void* d_out, int out_size) {
    const float* x      = (const float*)d_in[0];
    const int*   ei     = (const int*)d_in[1];
    const int*   etype  = (const int*)d_in[2];
    const float* w1     = (const float*)d_in[3];
    const float* root1  = (const float*)d_in[4];
    const float* b1     = (const float*)d_in[5];
    const float* gamma1 = (const float*)d_in[6];
    const float* beta1  = (const float*)d_in[7];
    const float* w2     = (const float*)d_in[8];
    const float* root2  = (const float*)d_in[9];
    const float* b2     = (const float*)d_in[10];
    float* out = (float*)d_out;

    __half *y;
    float *h, *acc, *scale, *shift;
    unsigned *cnt, *off, *woff, *bsum;
    int *ssrc;
    __half *wp1, *wp2;
    cudaGetSymbolAddress((void**)&y, g_y);
    cudaGetSymbolAddress((void**)&h, g_h);
    cudaGetSymbolAddress((void**)&cnt, g_cnt);
    cudaGetSymbolAddress((void**)&off, g_off);
    cudaGetSymbolAddress((void**)&woff, g_woff);
    cudaGetSymbolAddress((void**)&bsum, g_bsum);
    cudaGetSymbolAddress((void**)&ssrc, g_ssrc);
    cudaGetSymbolAddress((void**)&acc, g_acc);
    cudaGetSymbolAddress((void**)&scale, g_scale);
    cudaGetSymbolAddress((void**)&shift, g_shift);
    cudaGetSymbolAddress((void**)&wp1, g_wp1);
    cudaGetSymbolAddress((void**)&wp2, g_wp2);

    cudaFuncSetAttribute(gemm_kernel<false>, cudaFuncAttributeMaxDynamicSharedMemorySize, SMEM_BYTES);
    cudaFuncSetAttribute(gemm_kernel<true>,  cudaFuncAttributeMaxDynamicSharedMemorySize, SMEM_BYTES);

    static cudaStream_t s2 = nullptr;
    static cudaEvent_t evFork = nullptr, evJoin = nullptr;
    if (!s2) {
        cudaStreamCreate(&s2);
        cudaEventCreateWithFlags(&evFork, cudaEventDisableTiming);
        cudaEventCreateWithFlags(&evJoin, cudaEventDisableTiming);
    }

    const int MT = (NN + 63) / 64;             // 1563
    const int NB1 = (NSEG + 2047) / 2048;      // 391
    const int WPN = (9 * 4096 + 255) / 256;    // 144

    cudaMemsetAsync(acc, 0, 128 * sizeof(float), 0);

    prep_w<<<WPN, 256>>>(w1, root1, wp1);                              // #1 (s0)

    // fork: prep_w2 + sort pipeline on s2 (overlap gemm1)
    cudaEventRecord(evFork, 0);
    cudaStreamWaitEvent(s2, evFork, 0);
    cudaMemsetAsync(cnt, 0, NSEG * sizeof(unsigned), s2);
    prep_w<<<WPN, 256, 0, s2>>>(w2, root2, wp2);                       // #2 (s2)
    hist_kernel<<<(EE + 255) / 256, 256, 0, s2>>>(ei, etype, cnt);     // #3 (s2)

    gemm_kernel<false><<<MT, 256, SMEM_BYTES>>>(x, wp1, b1, nullptr, nullptr, y, h); // #4 (profiled)

    scan1<<<NB1, 256, 0, s2>>>(cnt, off, bsum);                        // #5
    scan2<<<1, 512, 0, s2>>>(bsum, NB1);                               // #6
    scan3<<<(NSEG + 255) / 256, 256, 0, s2>>>(off, woff, bsum);        // #7
    sort_kernel<<<(EE + 255) / 256, 256, 0, s2>>>(ei, etype, woff, ssrc); // #8
    cudaEventRecord(evJoin, s2);
    cudaStreamWaitEvent(0, evJoin, 0);

    scatter_kernel<true><<<NN / 8, 256>>>(y, off, ssrc, h, acc);       // #9 (fused BN stats)
    bn_final<<<1, 64>>>(acc, gamma1, beta1, scale, shift);             // #10
    gemm_kernel<true><<<MT, 256, SMEM_BYTES>>>(h, wp2, b2, scale, shift, y, out); // #11
    scatter_kernel<false><<<NN / 8, 256>>>(y, off, ssrc, out, nullptr); // #12
}